// round 17
// baseline (speedup 1.0000x reference)
#include <cuda_runtime.h>
#include <cuda_fp16.h>
#include <cstdint>
#include <cstring>

#define NN 100000
#define KK 2
#define EMAX 1600000
#define SCAN_CHUNK 512
#define NB_SCAN ((NN + SCAN_CHUNK - 1) / SCAN_CHUNK)   // 196

// ---------------- scratch (static device globals; no allocation) -------------
__device__ float g_dinv[NN];
__device__ int   g_cnt[NN];
__device__ int   g_off[NN + 1];
__device__ int   g_cur[NN];
__device__ int   g_bsum[256];
__device__ int   g_boff[256];
__device__ int2  g_edge[EMAX];                       // (row, norm), CSR by col
__device__ float g_bufT[(size_t)KK * NN * 64 + 64];  // fp16 gather src
__device__ float g_bufA[(size_t)KK * NN * 64 + 64];  // root terms (fp32)
__device__ float g_h[(size_t)NN * 64 + 64];          // layer-1 output (fp32)
__device__ float g_bufC[(size_t)KK * NN * 64 + 64];  // root terms (fp32)
__device__ float g_bufD[(size_t)KK * NN * 64 + 64];  // fp16 message sums

__device__ __forceinline__ float* sel_buf(int s) {
    return s == 0 ? g_bufT
         : (s == 1 ? g_bufA
         : (s == 2 ? g_h
         : (s == 3 ? g_bufC : g_bufD)));
}

// ---------------- fp16 helpers -----------------------------------------------
__device__ __forceinline__ uint32_t h2u(__half2 h) {
    uint32_t u;
    memcpy(&u, &h, 4);
    return u;
}

// m16n8k16 f16 MMA, f32 accumulate
__device__ __forceinline__ void mma16(float* d, const uint32_t* a,
                                      uint32_t b0, uint32_t b1) {
    asm("mma.sync.aligned.m16n8k16.row.col.f32.f16.f16.f32 "
        "{%0,%1,%2,%3}, {%4,%5,%6,%7}, {%8,%9}, {%0,%1,%2,%3};"
        : "+f"(d[0]), "+f"(d[1]), "+f"(d[2]), "+f"(d[3])
        : "r"(a[0]), "r"(a[1]), "r"(a[2]), "r"(a[3]), "r"(b0), "r"(b1));
}

// ---------------- prep: degree, CSR build ------------------------------------
__global__ void zero_cnt_kernel() {
    int n = blockIdx.x * blockDim.x + threadIdx.x;
    if (n < NN) g_cnt[n] = 0;
}

__global__ void count_kernel(const int* __restrict__ col, int E) {
    int e = blockIdx.x * blockDim.x + threadIdx.x;
    if (e < E) atomicAdd(&g_cnt[col[e]], 1);
}

__global__ void dinv_kernel() {
    int n = blockIdx.x * blockDim.x + threadIdx.x;
    if (n < NN) {
        int c = g_cnt[n];
        g_dinv[n] = c > 0 ? rsqrtf((float)c) : 0.0f;
    }
}

__global__ void scanA_kernel() {
    __shared__ int s[SCAN_CHUNK];
    int t = threadIdx.x;
    int i = blockIdx.x * SCAN_CHUNK + t;
    s[t] = (i < NN) ? g_cnt[i] : 0;
    __syncthreads();
    for (int o = SCAN_CHUNK / 2; o > 0; o >>= 1) {
        if (t < o) s[t] += s[t + o];
        __syncthreads();
    }
    if (t == 0) g_bsum[blockIdx.x] = s[0];
}

__global__ void scanB_kernel() {
    __shared__ int s[256];
    int t = threadIdx.x;
    int val = (t < NB_SCAN) ? g_bsum[t] : 0;
    s[t] = val;
    __syncthreads();
    for (int o = 1; o < 256; o <<= 1) {
        int add = (t >= o) ? s[t - o] : 0;
        __syncthreads();
        s[t] += add;
        __syncthreads();
    }
    g_boff[t] = s[t] - val;
    if (t == NB_SCAN - 1) g_off[NN] = s[t];
}

__global__ void scanC_kernel() {
    __shared__ int s[SCAN_CHUNK];
    int t = threadIdx.x;
    int i = blockIdx.x * SCAN_CHUNK + t;
    int val = (i < NN) ? g_cnt[i] : 0;
    s[t] = val;
    __syncthreads();
    for (int o = 1; o < SCAN_CHUNK; o <<= 1) {
        int add = (t >= o) ? s[t - o] : 0;
        __syncthreads();
        s[t] += add;
        __syncthreads();
    }
    if (i < NN) {
        int excl = s[t] - val + g_boff[blockIdx.x];
        g_off[i] = excl;
        g_cur[i] = excl;
    }
}

__global__ void fill_kernel(const int* __restrict__ ei, int E) {
    int e = blockIdx.x * blockDim.x + threadIdx.x;
    if (e < E) {
        int r = ei[e];
        int c = ei[(size_t)E + e];
        float nrm = g_dinv[r] * g_dinv[c];
        int pos = atomicAdd(&g_cur[c], 1);
        g_edge[pos] = make_int2(r, __float_as_int(nrm));
    }
}

// ---------------- tensor-core GEMM (fp16 3-term split, m16n8k16) -------------
// koff: runtime k-offset (launch gridDim.y=1 for per-k split launches).
// RELU2: A = relu(src + g_bufD[fp16]).  OUTH: fp16 output (gather-src path).
template <int FP, int FS, int GP, bool PERK, bool RELUIN, bool RELU2,
          bool HASB, bool OUTH, int SRCSEL, int DSTSEL>
__global__ void gemm_tc(const float* __restrict__ Xext,
                        const float* __restrict__ W, int Fl, int Gl,
                        const float* __restrict__ Bias, int Bk, int koff) {
    constexpr int NCH = GP / 8;
    constexpr int KST = FP / 16;
    constexpr int BST = GP + 4;          // u64 row stride of pair arrays

    extern __shared__ unsigned char dsm_raw[];
    uint2* Wph = (uint2*)dsm_raw;                   // (FP/4)*BST u64 entries
    uint2* Wpl = Wph + (FP / 4) * BST;
    float* Bsm = (float*)(Wpl + (FP / 4) * BST);

    const float* __restrict__ X = (SRCSEL < 0) ? Xext : sel_buf(SRCSEL);
    float* __restrict__ OUT = sel_buf(DSTSEL);

    const int kk = blockIdx.y + koff;
    const int tid = threadIdx.x;
    const int wid = tid >> 5;
    const int lane = tid & 31;
    const int r0 = lane >> 2;    // 0..7
    const int c0 = lane & 3;     // 0..3

    // stage W as fp16 hi/lo, k-packed for m16n8k16 B fragments
    for (int i = tid; i < FP * GP; i += 256) {
        int f = i / GP, g = i % GP;
        float w = (f < Fl && g < Gl)
                      ? W[(size_t)kk * Fl * Gl + (size_t)f * Gl + g]
                      : 0.0f;
        __half hi = __float2half_rn(w);
        __half lo = __float2half_rn(w - __half2float(hi));
        int ks = f >> 4;
        int kc = f & 15;
        int pair = kc >> 1;          // 0..7
        int j = pair >> 2;           // uint2 slot
        int row = ks * 4 + (pair & 3);
        int hp = kc & 1;
        size_t hidx = ((size_t)(row * BST + g) * 2 + j) * 2 + hp;
        ((__half*)Wph)[hidx] = hi;
        ((__half*)Wpl)[hidx] = lo;
    }
    if (tid < GP) Bsm[tid] = (HASB && tid < Gl) ? Bias[(size_t)kk * Bk + tid] : 0.0f;
    __syncthreads();

    const int mbase = blockIdx.x * 256 + wid * 32;

    const float* xp[4];
    const __half* xqh[4];
#pragma unroll
    for (int t = 0; t < 4; t++) {
        int n = mbase + t * 8 + r0;
        int nc = n < NN ? n : NN - 1;
        size_t off = PERK ? ((size_t)kk * NN + nc) * FS : (size_t)nc * FS;
        xp[t] = X + off;
        if (RELU2) xqh[t] = (const __half*)g_bufD + off;
    }

    float acc[2][NCH][4];
#pragma unroll
    for (int t = 0; t < 2; t++)
#pragma unroll
        for (int nc = 0; nc < NCH; nc++)
#pragma unroll
            for (int q = 0; q < 4; q++) acc[t][nc][q] = 0.0f;

#pragma unroll
    for (int ks = 0; ks < KST; ks++) {
        const int kb = ks * 16;
        uint32_t ahi[2][4], alo[2][4];
#pragma unroll
        for (int t = 0; t < 2; t++) {
            float2 pA0 = *(const float2*)(xp[2 * t + 0] + kb + 2 * c0);
            float2 pB0 = *(const float2*)(xp[2 * t + 1] + kb + 2 * c0);
            float2 pA1 = *(const float2*)(xp[2 * t + 0] + kb + 2 * c0 + 8);
            float2 pB1 = *(const float2*)(xp[2 * t + 1] + kb + 2 * c0 + 8);
            if (RELU2) {
                float2 q;
                q = __half22float2(*(const __half2*)(xqh[2 * t + 0] + kb + 2 * c0));
                pA0.x += q.x; pA0.y += q.y;
                q = __half22float2(*(const __half2*)(xqh[2 * t + 1] + kb + 2 * c0));
                pB0.x += q.x; pB0.y += q.y;
                q = __half22float2(*(const __half2*)(xqh[2 * t + 0] + kb + 2 * c0 + 8));
                pA1.x += q.x; pA1.y += q.y;
                q = __half22float2(*(const __half2*)(xqh[2 * t + 1] + kb + 2 * c0 + 8));
                pB1.x += q.x; pB1.y += q.y;
            }
            float2 vv[4] = {pA0, pB0, pA1, pB1};
#pragma unroll
            for (int q = 0; q < 4; q++) {
                float vx = vv[q].x, vy = vv[q].y;
                if (RELUIN) { vx = fmaxf(vx, 0.f); vy = fmaxf(vy, 0.f); }
                __half2 hi2 = __floats2half2_rn(vx, vy);
                float2 hf = __half22float2(hi2);
                __half2 lo2 = __floats2half2_rn(vx - hf.x, vy - hf.y);
                ahi[t][q] = h2u(hi2);
                alo[t][q] = h2u(lo2);
            }
        }
#pragma unroll
        for (int nc = 0; nc < NCH; nc++) {
            const int bidx = (ks * 4 + c0) * BST + nc * 8 + r0;
            uint2 bh = Wph[bidx];
            uint2 bl = Wpl[bidx];
#pragma unroll
            for (int t = 0; t < 2; t++) {
                mma16(acc[t][nc], ahi[t], bh.x, bh.y);
                mma16(acc[t][nc], alo[t], bh.x, bh.y);
                mma16(acc[t][nc], ahi[t], bl.x, bl.y);
            }
        }
    }

#pragma unroll
    for (int t = 0; t < 2; t++) {
#pragma unroll
        for (int nc = 0; nc < NCH; nc++) {
            const int col = nc * 8 + 2 * c0;
            const float bx = Bsm[col], by = Bsm[col + 1];
            const int rowA = mbase + t * 16 + r0;
            const int rowB = rowA + 8;
            if (rowA < NN) {
                float vx = acc[t][nc][0] + bx, vy = acc[t][nc][1] + by;
                if (OUTH) {
                    __half2* o = (__half2*)((__half*)OUT +
                        ((size_t)kk * NN + rowA) * GP + col);
                    *o = __floats2half2_rn(vx, vy);
                } else {
                    *(float2*)(OUT + ((size_t)kk * NN + rowA) * GP + col) =
                        make_float2(vx, vy);
                }
            }
            if (rowB < NN) {
                float vx = acc[t][nc][2] + bx, vy = acc[t][nc][3] + by;
                if (OUTH) {
                    __half2* o = (__half2*)((__half*)OUT +
                        ((size_t)kk * NN + rowB) * GP + col);
                    *o = __floats2half2_rn(vx, vy);
                } else {
                    *(float2*)(OUT + ((size_t)kk * NN + rowB) * GP + col) =
                        make_float2(vx, vy);
                }
            }
        }
    }
}

static inline int gemm_smem_bytes(int FP, int GP) {
    return 2 * (FP / 4) * (GP + 4) * 8 + GP * 4;   // all < 48 KB
}

// ---------------- CSR gather (fp16 src) --------------------------------------
// KSPLIT: k fixed (runtime kfix), ITEMS=G4 per node — enables k-pipelining.
// PUREMSG: write raw message sum as fp16 into dst (no read).
// COMBINE: read dst (fp32 root), add, relu, k-mean via shfl_xor(16) -> g_h.
template <int G4, int SRCSEL, int DSTSEL, bool COMBINE, bool PUREMSG,
          bool KSPLIT>
__global__ void gather_kernel(int kfix) {
    const __half* __restrict__ src = (const __half*)sel_buf(SRCSEL);
    float* __restrict__ dst = sel_buf(DSTSEL);

    constexpr int ITEMS = KSPLIT ? G4 : (KK * G4);
    const long long t = blockIdx.x * (long long)blockDim.x + threadIdx.x;
    const int n = (int)(t / ITEMS);
    if (n >= NN) return;
    const int rem = (int)(t - (long long)n * ITEMS);
    const int k = KSPLIT ? kfix : (rem / G4);
    const int j = KSPLIT ? rem : (rem - (rem / G4) * G4);

    int p = g_off[n];
    const int end = g_off[n + 1];

    const __half* srcb = src + (size_t)k * NN * (G4 * 4);
    float4 acc = make_float4(0.f, 0.f, 0.f, 0.f);

#define GATH_LOAD(vv, ee)                                                     \
    {                                                                         \
        const __half2* hp = (const __half2*)(srcb +                           \
            (size_t)(ee).x * (G4 * 4) + j * 4);                               \
        float2 a = __half22float2(hp[0]);                                     \
        float2 b = __half22float2(hp[1]);                                     \
        vv = make_float4(a.x, a.y, b.x, b.y);                                 \
    }

    for (; p + 3 < end; p += 4) {
        int2 e0 = g_edge[p];
        int2 e1 = g_edge[p + 1];
        int2 e2 = g_edge[p + 2];
        int2 e3 = g_edge[p + 3];
        float4 v0, v1, v2, v3;
        GATH_LOAD(v0, e0) GATH_LOAD(v1, e1) GATH_LOAD(v2, e2) GATH_LOAD(v3, e3)
        float n0 = __int_as_float(e0.y);
        float n1 = __int_as_float(e1.y);
        float n2 = __int_as_float(e2.y);
        float n3 = __int_as_float(e3.y);
        acc.x += v0.x * n0 + v1.x * n1 + v2.x * n2 + v3.x * n3;
        acc.y += v0.y * n0 + v1.y * n1 + v2.y * n2 + v3.y * n3;
        acc.z += v0.z * n0 + v1.z * n1 + v2.z * n2 + v3.z * n3;
        acc.w += v0.w * n0 + v1.w * n1 + v2.w * n2 + v3.w * n3;
    }
    for (; p < end; p++) {
        int2 e0 = g_edge[p];
        float4 v0;
        GATH_LOAD(v0, e0)
        float n0 = __int_as_float(e0.y);
        acc.x += v0.x * n0; acc.y += v0.y * n0;
        acc.z += v0.z * n0; acc.w += v0.w * n0;
    }
#undef GATH_LOAD

    if (PUREMSG) {
        // fp16 message store (uint2 = 4 halfs)
        uint2 st;
        st.x = h2u(__floats2half2_rn(acc.x, acc.y));
        st.y = h2u(__floats2half2_rn(acc.z, acc.w));
        *(uint2*)((__half*)dst + ((size_t)k * NN + n) * (G4 * 4) + j * 4) = st;
        return;
    }

    float4* dp = (float4*)(dst + ((size_t)k * NN + n) * (G4 * 4)) + j;
    float4 cur = *dp;
    cur.x += acc.x; cur.y += acc.y; cur.z += acc.z; cur.w += acc.w;

    if (COMBINE) {
        float4 r = make_float4(fmaxf(cur.x, 0.f), fmaxf(cur.y, 0.f),
                               fmaxf(cur.z, 0.f), fmaxf(cur.w, 0.f));
        float4 o;
        o.x = __shfl_xor_sync(0xFFFFFFFFu, r.x, 16);
        o.y = __shfl_xor_sync(0xFFFFFFFFu, r.y, 16);
        o.z = __shfl_xor_sync(0xFFFFFFFFu, r.z, 16);
        o.w = __shfl_xor_sync(0xFFFFFFFFu, r.w, 16);
        if (k == 0) {
            float4 hv = make_float4(0.5f * (r.x + o.x), 0.5f * (r.y + o.y),
                                    0.5f * (r.z + o.z), 0.5f * (r.w + o.w));
            *((float4*)(g_h + (size_t)n * 64) + j) = hv;
        }
    } else {
        *dp = cur;
    }
}

// ---------------- final: mean_k relu + log_softmax (C=41, stride 48) ---------
__global__ void final_kernel(float* __restrict__ out) {
    const int warp = (int)((blockIdx.x * (size_t)blockDim.x + threadIdx.x) >> 5);
    const int lane = threadIdx.x & 31;
    if (warp >= NN) return;

    const size_t b0 = (size_t)warp * 48;
    const size_t b1 = ((size_t)NN + warp) * 48;

    float v1 = -1e30f, v2 = -1e30f;
    if (lane < 41)
        v1 = 0.5f * (fmaxf(g_bufC[b0 + lane], 0.f) + fmaxf(g_bufC[b1 + lane], 0.f));
    if (lane + 32 < 41)
        v2 = 0.5f * (fmaxf(g_bufC[b0 + lane + 32], 0.f) + fmaxf(g_bufC[b1 + lane + 32], 0.f));

    float m = fmaxf(v1, v2);
#pragma unroll
    for (int o = 16; o; o >>= 1) m = fmaxf(m, __shfl_xor_sync(0xFFFFFFFFu, m, o));

    float s = 0.f;
    if (lane < 41) s += expf(v1 - m);
    if (lane + 32 < 41) s += expf(v2 - m);
#pragma unroll
    for (int o = 16; o; o >>= 1) s += __shfl_xor_sync(0xFFFFFFFFu, s, o);

    const float l = m + logf(s);
    if (lane < 41) out[(size_t)warp * 41 + lane] = v1 - l;
    if (lane + 32 < 41) out[(size_t)warp * 41 + lane + 32] = v2 - l;
}

// ---------------- host driver: k-pipelined 3-stream schedule -----------------
extern "C" void kernel_launch(void* const* d_in, const int* in_sizes, int n_in,
                              void* d_out, int out_size) {
    const float* x       = (const float*)d_in[0];
    const int*   ei      = (const int*)d_in[1];   // int32 (JAX x64 disabled)
    const float* w1_init = (const float*)d_in[2];
    const float* w1_mid  = (const float*)d_in[3];  // [1,K,64,64]
    const float* w1_root = (const float*)d_in[4];  // [2,K,128,64]
    const float* b1      = (const float*)d_in[5];  // [2,K,1,64]
    const float* w2_init = (const float*)d_in[6];
    const float* w2_mid  = (const float*)d_in[7];  // [1,K,41,41]
    const float* w2_root = (const float*)d_in[8];  // [2,K,64,41]
    const float* b2      = (const float*)d_in[9];  // [2,K,1,41]
    float* out = (float*)d_out;
    const int E = in_sizes[1] / 2;

    static bool inited = false;
    static cudaStream_t s1, s2;
    static cudaEvent_t evFork, evFill, evI0, evG1A, evR0, evR1, evCH,
                       evR2, evR3, evI2, evG3A, evM2A, evG4A, evJ1;
    if (!inited) {
        cudaStreamCreateWithFlags(&s1, cudaStreamNonBlocking);
        cudaStreamCreateWithFlags(&s2, cudaStreamNonBlocking);
        cudaEvent_t* evs[] = {&evFork, &evFill, &evI0, &evG1A, &evR0, &evR1,
                              &evCH, &evR2, &evR3, &evI2, &evG3A, &evM2A,
                              &evG4A, &evJ1};
        for (auto e : evs) cudaEventCreateWithFlags(e, cudaEventDisableTiming);
        inited = true;
    }

    const int nb_n   = (NN + 255) / 256;
    const int nb_e   = (E + 255) / 256;
    const int nb_g1  = (int)(((long long)NN * 32 + 255) / 256);  // full, G4=16
    const int nb_g1s = (int)(((long long)NN * 16 + 255) / 256);  // split, G4=16
    const int nb_g2s = (int)(((long long)NN * 12 + 255) / 256);  // split, G4=12

    const dim3 g_full((NN + 255) / 256, KK);
    const dim3 g_half((NN + 255) / 256, 1);

    const int sm_128_64 = gemm_smem_bytes(128, 64);
    const int sm_64_64  = gemm_smem_bytes(64, 64);
    const int sm_64_48  = gemm_smem_bytes(64, 48);
    const int sm_48_48  = gemm_smem_bytes(48, 48);

    // ---- fork side streams from the (capturing) origin stream --------------
    cudaEventRecord(evFork, 0);
    cudaStreamWaitEvent(s1, evFork, 0);
    cudaStreamWaitEvent(s2, evFork, 0);

    // s2: prep head (launch idx 0-2)
    zero_cnt_kernel<<<nb_n, 256, 0, s2>>>();
    count_kernel<<<nb_e, 256, 0, s2>>>(ei + E, E);
    dinv_kernel<<<nb_n, 256, 0, s2>>>();

    // s0: init_k0 (launch idx 3 — profiled), init_k1
    gemm_tc<128, 128, 64, false, false, false, false, true, -1, 0>
        <<<g_half, 256, sm_128_64>>>(x, w1_init, 128, 64, nullptr, 0, 0);
    cudaEventRecord(evI0, 0);
    gemm_tc<128, 128, 64, false, false, false, false, true, -1, 0>
        <<<g_half, 256, sm_128_64>>>(x, w1_init, 128, 64, nullptr, 0, 1);

    // s2: rest of CSR build, then GA1_k0 (after fill in-stream, init_k0 via ev)
    scanA_kernel<<<NB_SCAN, SCAN_CHUNK, 0, s2>>>();
    scanB_kernel<<<1, 256, 0, s2>>>();
    scanC_kernel<<<NB_SCAN, SCAN_CHUNK, 0, s2>>>();
    fill_kernel<<<nb_e, 256, 0, s2>>>(ei, E);
    cudaEventRecord(evFill, s2);
    cudaStreamWaitEvent(s2, evI0, 0);
    gather_kernel<16, 0, 4, false, true, true><<<nb_g1s, 256, 0, s2>>>(0);
    cudaEventRecord(evG1A, s2);

    // s1: root0 (x->bufA), root1 (x->bufC) — full-K
    gemm_tc<128, 128, 64, false, false, false, true, false, -1, 1>
        <<<g_full, 256, sm_128_64, s1>>>(x, w1_root, 128, 64, b1, 64, 0);
    cudaEventRecord(evR0, s1);
    gemm_tc<128, 128, 64, false, false, false, true, false, -1, 3>
        <<<g_full, 256, sm_128_64, s1>>>(x, w1_root + (size_t)2 * 128 * 64,
                                         128, 64, b1 + 2 * 64, 64, 0);
    cudaEventRecord(evR1, s1);

    // s0: GA1_k1 (init_k1 in-stream; fill via event), then mid, GA2
    cudaStreamWaitEvent(0, evFill, 0);
    gather_kernel<16, 0, 4, false, true, true><<<nb_g1s, 256>>>(1);
    cudaStreamWaitEvent(0, evG1A, 0);
    cudaStreamWaitEvent(0, evR0, 0);
    gemm_tc<64, 64, 64, true, true, true, false, true, 1, 0>   // relu(bufA+bufD)
        <<<g_full, 256, sm_64_64>>>(nullptr, w1_mid, 64, 64, nullptr, 0, 0);
    cudaStreamWaitEvent(0, evR1, 0);
    gather_kernel<16, 0, 3, true, false, false><<<nb_g1, 256>>>(0);  // -> h
    cudaEventRecord(evCH, 0);

    // s1: layer-2 root GEMMs (depend on h)
    cudaStreamWaitEvent(s1, evCH, 0);
    gemm_tc<64, 64, 48, false, false, false, true, false, 2, 1>
        <<<g_full, 256, sm_64_48, s1>>>(nullptr, w2_root, 64, 41, b2, 41, 0);
    cudaEventRecord(evR2, s1);
    gemm_tc<64, 64, 48, false, false, false, true, false, 2, 3>
        <<<g_full, 256, sm_64_48, s1>>>(nullptr, w2_root + (size_t)2 * 64 * 41,
                                        64, 41, b2 + 2 * 41, 41, 0);
    cudaEventRecord(evR3, s1);

    // s0: init2 split; GA3 split pipelined (k0 on s2, k1 on s0)
    gemm_tc<64, 64, 48, false, false, false, false, true, 2, 0>
        <<<g_half, 256, sm_64_48>>>(nullptr, w2_init, 64, 41, nullptr, 0, 0);
    cudaEventRecord(evI2, 0);
    gemm_tc<64, 64, 48, false, false, false, false, true, 2, 0>
        <<<g_half, 256, sm_64_48>>>(nullptr, w2_init, 64, 41, nullptr, 0, 1);
    gather_kernel<12, 0, 4, false, true, true><<<nb_g2s, 256>>>(1);
    cudaStreamWaitEvent(s2, evI2, 0);
    gather_kernel<12, 0, 4, false, true, true><<<nb_g2s, 256, 0, s2>>>(0);
    cudaEventRecord(evG3A, s2);

    // s0: mid2 split; GA4 split pipelined (k0 on s2, k1 on s0); final
    cudaStreamWaitEvent(0, evG3A, 0);
    cudaStreamWaitEvent(0, evR2, 0);
    gemm_tc<48, 48, 48, true, true, true, false, true, 1, 0>
        <<<g_half, 256, sm_48_48>>>(nullptr, w2_mid, 41, 41, nullptr, 0, 0);
    cudaEventRecord(evM2A, 0);
    gemm_tc<48, 48, 48, true, true, true, false, true, 1, 0>
        <<<g_half, 256, sm_48_48>>>(nullptr, w2_mid, 41, 41, nullptr, 0, 1);
    cudaStreamWaitEvent(s2, evM2A, 0);
    cudaStreamWaitEvent(s2, evR3, 0);
    gather_kernel<12, 0, 3, false, false, true><<<nb_g2s, 256, 0, s2>>>(0);
    cudaEventRecord(evG4A, s2);
    cudaStreamWaitEvent(0, evR3, 0);
    gather_kernel<12, 0, 3, false, false, true><<<nb_g2s, 256>>>(1);
    cudaStreamWaitEvent(0, evG4A, 0);
    final_kernel<<<(NN * 32 + 255) / 256, 256>>>(out);

    // ---- join side streams back into the origin stream ---------------------
    cudaEventRecord(evJ1, s1);
    cudaStreamWaitEvent(0, evJ1, 0);
}